// round 10
// baseline (speedup 1.0000x reference)
#include <cuda_runtime.h>
#include <cuda_bf16.h>
#include <mma.h>
#include <math.h>

using namespace nvcuda;

#define TT     1024
#define CC     1024
#define NHEAD  16
#define NKVH   4
#define HDIM   64
#define QKVN   1536   // 1024 + 256 + 256
#define HIDN   2736
#define HP     2816   // padded hidden (22*128)
#define NLAYER 4
#define NEXP   8
#define TOPK   2
#define VOCAB  32000

// dynamic smem sizes (bytes)
#define SMEM_G64   ((2*64*40  + 2*16*264) * 4)   // 54272
#define SMEM_G128  ((2*128*40 + 2*16*264) * 4)   // 74752
#define SMEM_ATT   (4 * 64 * 68 * 4)             // 69632

// ---------------- scratch ----------------
__device__ float g_x   [TT*CC];
__device__ float g_h   [TT*CC];
__device__ float g_qkv [TT*QKVN];
__device__ float g_wqkv[CC*QKVN];
__device__ float g_s   [(size_t)NHEAD*TT*TT];
__device__ float g_o   [TT*CC];
__device__ float g_t   [TT*CC];
__device__ float g_m1  [TT*HP];
__device__ float g_m2  [TT*HP];
__device__ float g_xe  [(size_t)NEXP*TT*CC];
__device__ float g_eg  [(size_t)NEXP*TT*HP];
__device__ float g_eu  [(size_t)NEXP*TT*HP];
__device__ float g_ey  [(size_t)NEXP*TT*CC];
__device__ int   g_cnt [NEXP];
__device__ int   g_topi[TT*TOPK];
__device__ float g_topw[TT*TOPK];
__device__ int   g_slot[TT*TOPK];

// ---------------- 3xTF32 wmma GEMM, hi/lo pre-split in smem ----------------
// C(MxN) = A(MxK) @ B(KxN). Each element split ONCE at staging:
//   hi = tf32(x), lo = tf32(x - hi);  a*b ~= ahi*bhi + alo*bhi + ahi*blo
// Mainloop contains only LDS + HMMA (no F2F/FSUB).
// Optional A2: A_eff = silu(A)*A2. Batched via blockIdx.z; cnt[] early-exit.
template<int BM>
__global__ void __launch_bounds__(256) wgemm_kernel(
    const float* __restrict__ A, const float* __restrict__ A2,
    const float* __restrict__ B, float* __restrict__ C,
    int N, int K, int lda, int ldc,
    size_t sA, size_t sB, size_t sC, const int* __restrict__ cnt)
{
    constexpr int BN = 128, BK = 16;
    constexpr int MFRAG = BM / 32;
    constexpr int A4 = BM / 64;
    constexpr int AROW = 40;             // hi[0..15] pad, lo at +20
    constexpr int BROW = 264;            // hi[0..127] pad, lo at +132
    constexpr int ASTG = BM * AROW;      // floats per A stage
    constexpr int BSTG = BK * BROW;      // floats per B stage

    const int bz = blockIdx.z;
    if (cnt && (int)(blockIdx.y * BM) >= cnt[bz]) return;

    const float* Ab  = A + (size_t)bz * sA + (size_t)blockIdx.y * BM * lda;
    const float* A2b = A2 ? (A2 + (size_t)bz * sA + (size_t)blockIdx.y * BM * lda) : nullptr;
    const float* Bb  = B + (size_t)bz * sB;
    float*       Cb  = C + (size_t)bz * sC + (size_t)blockIdx.y * BM * ldc + (size_t)blockIdx.x * BN;
    const int n0 = blockIdx.x * BN;

    extern __shared__ float sm[];
    float* Asm = sm;                 // [2][BM][40]
    float* Bsm = sm + 2 * ASTG;      // [2][BK][264]

    const int tid = threadIdx.x;
    const int wid = tid >> 5;
    const int wm  = wid >> 2;
    const int wn  = wid & 3;

    wmma::fragment<wmma::accumulator, 16, 16, 8, float> acc[MFRAG][2];
    #pragma unroll
    for (int i = 0; i < MFRAG; i++)
        #pragma unroll
        for (int j = 0; j < 2; j++)
            wmma::fill_fragment(acc[i][j], 0.0f);

    const int KT = K / BK;
    float4 ra[A4], rb[2];

    auto loadA = [&](int kt) {
        #pragma unroll
        for (int u = 0; u < A4; u++) {
            int f = tid + u * 256;
            int row = f >> 2, c4 = f & 3;
            float4 v = *(const float4*)(Ab + (size_t)row * lda + kt * BK + c4 * 4);
            if (A2b) {
                float4 v2 = *(const float4*)(A2b + (size_t)row * lda + kt * BK + c4 * 4);
                v.x = (v.x / (1.0f + expf(-v.x))) * v2.x;
                v.y = (v.y / (1.0f + expf(-v.y))) * v2.y;
                v.z = (v.z / (1.0f + expf(-v.z))) * v2.z;
                v.w = (v.w / (1.0f + expf(-v.w))) * v2.w;
            }
            ra[u] = v;
        }
    };
    auto loadB = [&](int kt) {
        #pragma unroll
        for (int u = 0; u < 2; u++) {
            int f = tid + u * 256;
            int row = f >> 5, c4 = f & 31;
            int col = n0 + c4 * 4;
            rb[u] = (col < N) ? *(const float4*)(Bb + (size_t)(kt * BK + row) * N + col)
                              : make_float4(0.f, 0.f, 0.f, 0.f);
        }
    };
    auto stA = [&](int buf) {
        #pragma unroll
        for (int u = 0; u < A4; u++) {
            int f = tid + u * 256;
            int row = f >> 2, c4 = f & 3;
            float4 v = ra[u], hi, lo;
            hi.x = wmma::__float_to_tf32(v.x); lo.x = wmma::__float_to_tf32(v.x - hi.x);
            hi.y = wmma::__float_to_tf32(v.y); lo.y = wmma::__float_to_tf32(v.y - hi.y);
            hi.z = wmma::__float_to_tf32(v.z); lo.z = wmma::__float_to_tf32(v.z - hi.z);
            hi.w = wmma::__float_to_tf32(v.w); lo.w = wmma::__float_to_tf32(v.w - hi.w);
            float* p = Asm + buf * ASTG + row * AROW + c4 * 4;
            *(float4*)p        = hi;
            *(float4*)(p + 20) = lo;
        }
    };
    auto stB = [&](int buf) {
        #pragma unroll
        for (int u = 0; u < 2; u++) {
            int f = tid + u * 256;
            int row = f >> 5, c4 = f & 31;
            float4 v = rb[u], hi, lo;
            hi.x = wmma::__float_to_tf32(v.x); lo.x = wmma::__float_to_tf32(v.x - hi.x);
            hi.y = wmma::__float_to_tf32(v.y); lo.y = wmma::__float_to_tf32(v.y - hi.y);
            hi.z = wmma::__float_to_tf32(v.z); lo.z = wmma::__float_to_tf32(v.z - hi.z);
            hi.w = wmma::__float_to_tf32(v.w); lo.w = wmma::__float_to_tf32(v.w - hi.w);
            float* p = Bsm + buf * BSTG + row * BROW + c4 * 4;
            *(float4*)p         = hi;
            *(float4*)(p + 132) = lo;
        }
    };

    loadA(0); loadB(0); stA(0); stB(0);
    __syncthreads();

    for (int kt = 0; kt < KT; kt++) {
        const int cur = kt & 1;
        if (kt + 1 < KT) { loadA(kt + 1); loadB(kt + 1); }

        #pragma unroll
        for (int ks = 0; ks < 2; ks++) {
            wmma::fragment<wmma::matrix_a, 16, 16, 8, wmma::precision::tf32, wmma::row_major> ahi[MFRAG], alo[MFRAG];
            wmma::fragment<wmma::matrix_b, 16, 16, 8, wmma::precision::tf32, wmma::row_major> bhi[2], blo[2];
            #pragma unroll
            for (int i = 0; i < MFRAG; i++) {
                const float* p = Asm + cur * ASTG + (wm * (BM / 2) + i * 16) * AROW + ks * 8;
                wmma::load_matrix_sync(ahi[i], p,      AROW);
                wmma::load_matrix_sync(alo[i], p + 20, AROW);
            }
            #pragma unroll
            for (int j = 0; j < 2; j++) {
                const float* p = Bsm + cur * BSTG + (ks * 8) * BROW + wn * 32 + j * 16;
                wmma::load_matrix_sync(bhi[j], p,       BROW);
                wmma::load_matrix_sync(blo[j], p + 132, BROW);
            }
            #pragma unroll
            for (int i = 0; i < MFRAG; i++)
                #pragma unroll
                for (int j = 0; j < 2; j++) {
                    wmma::mma_sync(acc[i][j], alo[i], bhi[j], acc[i][j]);
                    wmma::mma_sync(acc[i][j], ahi[i], blo[j], acc[i][j]);
                    wmma::mma_sync(acc[i][j], ahi[i], bhi[j], acc[i][j]);
                }
        }

        if (kt + 1 < KT) { stA(1 - cur); stB(1 - cur); }
        __syncthreads();
    }

    #pragma unroll
    for (int i = 0; i < MFRAG; i++)
        #pragma unroll
        for (int j = 0; j < 2; j++)
            wmma::store_matrix_sync(Cb + (size_t)(wm * (BM / 2) + i * 16) * ldc + wn * 32 + j * 16,
                                    acc[i][j], ldc, wmma::mem_row_major);
}

// ---------------- small ops ----------------
__global__ void pack_qkv_kernel(const float* __restrict__ Wq, const float* __restrict__ Wk,
                                const float* __restrict__ Wv)
{
    int r = blockIdx.x;
    for (int c = threadIdx.x; c < QKVN; c += 256) {
        float v;
        if (c < 1024)      v = Wq[(size_t)r * CC + c];
        else if (c < 1280) v = Wk[(size_t)r * 256 + (c - 1024)];
        else               v = Wv[(size_t)r * 256 + (c - 1280)];
        g_wqkv[(size_t)r * QKVN + c] = v;
    }
}

__global__ void embed_kernel(const int* __restrict__ idx, const float* __restrict__ wte)
{
    int t = blockIdx.x;
    int r = idx[t];
    for (int i = threadIdx.x; i < CC; i += 256)
        g_x[(size_t)t * CC + i] = wte[(size_t)r * CC + i];
}

__global__ void rmsnorm_kernel(const float* __restrict__ x, const float* __restrict__ w,
                               float* __restrict__ o)
{
    int t = blockIdx.x, tid = threadIdx.x;
    const float* xr = x + (size_t)t * CC;
    __shared__ float red[256];
    float s = 0.0f;
    for (int i = tid; i < CC; i += 256) { float v = xr[i]; s += v * v; }
    red[tid] = s; __syncthreads();
    for (int st = 128; st; st >>= 1) { if (tid < st) red[tid] += red[tid + st]; __syncthreads(); }
    float scale = rsqrtf(red[0] / CC + 1e-6f);
    for (int i = tid; i < CC; i += 256)
        o[(size_t)t * CC + i] = xr[i] * scale * w[i];
}

__global__ void add_kernel(float* __restrict__ y, const float* __restrict__ a, int n)
{
    int i = blockIdx.x * 256 + threadIdx.x;
    if (i < n) y[i] += a[i];
}

__global__ void rope_kernel(float* __restrict__ buf, int ld)   // grid (T, nheads), 32 thr
{
    int t = blockIdx.x, h = blockIdx.y, j = threadIdx.x;
    float inv = powf(10000.0f, -(float)j / 32.0f);
    float ang = (float)t * inv;
    float c = cosf(ang), sn = sinf(ang);
    float* p = buf + (size_t)t * ld + h * HDIM;
    float a = p[j], b = p[j + 32];
    p[j]      = a * c - b * sn;
    p[j + 32] = a * sn + b * c;
}

// ---------------- attention: split-tf32 wmma scores / PV ----------------
// scores: S(64x64) = Q_tile @ K_tile^T (K^T via col_major B frags), causal+scale
__global__ void __launch_bounds__(256) attn_scores_w()   // grid (kt, qt, NHEAD)
{
    int kt = blockIdx.x, qt = blockIdx.y, h = blockIdx.z;
    if (kt > qt) return;
    extern __shared__ float sm[];
    float* Qh = sm;
    float* Ql = sm + 64 * 68;
    float* Kh = sm + 2 * 64 * 68;
    float* Kl = sm + 3 * 64 * 68;
    int tid = threadIdx.x;
    const float* qb = g_qkv + (size_t)qt * 64 * QKVN + h * HDIM;
    const float* kb = g_qkv + 1024 + (size_t)kt * 64 * QKVN + (h >> 2) * HDIM;

    for (int i = tid; i < 4096; i += 256) {
        int m = i >> 6, d = i & 63;
        float q  = qb[(size_t)m * QKVN + d];
        float qh = wmma::__float_to_tf32(q);
        Qh[m * 68 + d] = qh;
        Ql[m * 68 + d] = wmma::__float_to_tf32(q - qh);
        float k  = kb[(size_t)m * QKVN + d];
        float kh = wmma::__float_to_tf32(k);
        Kh[m * 68 + d] = kh;
        Kl[m * 68 + d] = wmma::__float_to_tf32(k - kh);
    }
    __syncthreads();

    int wid = tid >> 5, wm = wid >> 2, wn = wid & 3;
    wmma::fragment<wmma::accumulator, 16, 16, 8, float> acc[2];
    wmma::fill_fragment(acc[0], 0.0f);
    wmma::fill_fragment(acc[1], 0.0f);

    #pragma unroll
    for (int kk = 0; kk < 8; kk++) {
        wmma::fragment<wmma::matrix_a, 16, 16, 8, wmma::precision::tf32, wmma::row_major> ahi[2], alo[2];
        wmma::fragment<wmma::matrix_b, 16, 16, 8, wmma::precision::tf32, wmma::col_major> bhi, blo;
        #pragma unroll
        for (int i = 0; i < 2; i++) {
            const float* p = Qh + (wm * 32 + i * 16) * 68 + kk * 8;
            wmma::load_matrix_sync(ahi[i], p, 68);
            wmma::load_matrix_sync(alo[i], Ql + (wm * 32 + i * 16) * 68 + kk * 8, 68);
        }
        wmma::load_matrix_sync(bhi, Kh + (wn * 16) * 68 + kk * 8, 68);
        wmma::load_matrix_sync(blo, Kl + (wn * 16) * 68 + kk * 8, 68);
        #pragma unroll
        for (int i = 0; i < 2; i++) {
            wmma::mma_sync(acc[i], alo[i], bhi, acc[i]);
            wmma::mma_sync(acc[i], ahi[i], blo, acc[i]);
            wmma::mma_sync(acc[i], ahi[i], bhi, acc[i]);
        }
    }
    __syncthreads();
    float* S = sm;   // reuse Qh/Ql area (64x68 needed)
    #pragma unroll
    for (int i = 0; i < 2; i++)
        wmma::store_matrix_sync(S + (wm * 32 + i * 16) * 68 + wn * 16, acc[i], 68, wmma::mem_row_major);
    __syncthreads();
    for (int i = tid; i < 4096; i += 256) {
        int m = i >> 6, d = i & 63;
        int qi = qt * 64 + m, ki = kt * 64 + d;
        g_s[((size_t)h * TT + qi) * TT + ki] = (ki <= qi) ? S[m * 68 + d] * 0.125f : -1e9f;
    }
}

// PV: O_tile(64x64) += sum_kt P_tile @ V_tile
__global__ void __launch_bounds__(256) attn_pv_w()       // grid (qt, NHEAD)
{
    int qt = blockIdx.x, h = blockIdx.y;
    extern __shared__ float sm[];
    float* Ph = sm;
    float* Pl = sm + 64 * 68;
    float* Vh = sm + 2 * 64 * 68;
    float* Vl = sm + 3 * 64 * 68;
    int tid = threadIdx.x;
    int wid = tid >> 5, wm = wid >> 2, wn = wid & 3;
    const float* pb = g_s + ((size_t)h * TT + (size_t)qt * 64) * TT;
    const float* vb = g_qkv + 1280 + (h >> 2) * HDIM;

    wmma::fragment<wmma::accumulator, 16, 16, 8, float> acc[2];
    wmma::fill_fragment(acc[0], 0.0f);
    wmma::fill_fragment(acc[1], 0.0f);

    for (int kt = 0; kt <= qt; kt++) {
        __syncthreads();
        for (int i = tid; i < 4096; i += 256) {
            int m = i >> 6, n = i & 63;
            float p  = pb[(size_t)m * TT + kt * 64 + n];
            float ph = wmma::__float_to_tf32(p);
            Ph[m * 68 + n] = ph;
            Pl[m * 68 + n] = wmma::__float_to_tf32(p - ph);
            float v  = vb[(size_t)(kt * 64 + m) * QKVN + n];
            float vh = wmma::__float_to_tf32(v);
            Vh[m * 68 + n] = vh;
            Vl[m * 68 + n] = wmma::__float_to_tf32(v - vh);
        }
        __syncthreads();
        #pragma unroll
        for (int kk = 0; kk < 8; kk++) {
            wmma::fragment<wmma::matrix_a, 16, 16, 8, wmma::precision::tf32, wmma::row_major> ahi[2], alo[2];
            wmma::fragment<wmma::matrix_b, 16, 16, 8, wmma::precision::tf32, wmma::row_major> bhi, blo;
            #pragma unroll
            for (int i = 0; i < 2; i++) {
                wmma::load_matrix_sync(ahi[i], Ph + (wm * 32 + i * 16) * 68 + kk * 8, 68);
                wmma::load_matrix_sync(alo[i], Pl + (wm * 32 + i * 16) * 68 + kk * 8, 68);
            }
            wmma::load_matrix_sync(bhi, Vh + (kk * 8) * 68 + wn * 16, 68);
            wmma::load_matrix_sync(blo, Vl + (kk * 8) * 68 + wn * 16, 68);
            #pragma unroll
            for (int i = 0; i < 2; i++) {
                wmma::mma_sync(acc[i], alo[i], bhi, acc[i]);
                wmma::mma_sync(acc[i], ahi[i], blo, acc[i]);
                wmma::mma_sync(acc[i], ahi[i], bhi, acc[i]);
            }
        }
    }
    #pragma unroll
    for (int i = 0; i < 2; i++)
        wmma::store_matrix_sync(g_o + (size_t)(qt * 64 + wm * 32 + i * 16) * CC + h * HDIM + wn * 16,
                                acc[i], CC, wmma::mem_row_major);
}

__global__ void softmax_kernel()         // grid (T, NHEAD), 256 thr
{
    int qi = blockIdx.x, h = blockIdx.y, tid = threadIdx.x;
    float* row = g_s + ((size_t)h * TT + qi) * TT;
    int len = ((qi >> 6) + 1) << 6;
    __shared__ float red[256];
    float m = -1e30f;
    for (int i = tid; i < len; i += 256) m = fmaxf(m, row[i]);
    red[tid] = m; __syncthreads();
    for (int st = 128; st; st >>= 1) { if (tid < st) red[tid] = fmaxf(red[tid], red[tid + st]); __syncthreads(); }
    m = red[0]; __syncthreads();
    float sum = 0.0f;
    for (int i = tid; i < len; i += 256) { float e = expf(row[i] - m); row[i] = e; sum += e; }
    red[tid] = sum; __syncthreads();
    for (int st = 128; st; st >>= 1) { if (tid < st) red[tid] += red[tid + st]; __syncthreads(); }
    float inv = 1.0f / red[0];
    for (int i = tid; i < len; i += 256) row[i] *= inv;
}

// ---------------- MoE routing ----------------
__global__ void reset_cnt_kernel()
{
    if (threadIdx.x < NEXP) g_cnt[threadIdx.x] = 0;
}

__global__ void gate_kernel(const float* __restrict__ h, const float* __restrict__ gw)
{
    int t = blockIdx.x, tid = threadIdx.x;
    __shared__ float red[128][NEXP];
    float acc[NEXP] = {};
    const float* hr = h + (size_t)t * CC;
    for (int c = tid; c < CC; c += 128) {
        float xv = hr[c];
        #pragma unroll
        for (int e = 0; e < NEXP; e++) acc[e] = fmaf(xv, gw[c * NEXP + e], acc[e]);
    }
    #pragma unroll
    for (int e = 0; e < NEXP; e++) red[tid][e] = acc[e];
    __syncthreads();
    for (int st = 64; st; st >>= 1) {
        if (tid < st)
            #pragma unroll
            for (int e = 0; e < NEXP; e++) red[tid][e] += red[tid + st][e];
        __syncthreads();
    }
    if (tid == 0) {
        float v[NEXP];
        #pragma unroll
        for (int e = 0; e < NEXP; e++) v[e] = red[0][e];
        int i0 = 0;
        for (int e = 1; e < NEXP; e++) if (v[e] > v[i0]) i0 = e;
        int i1 = -1;
        for (int e = 0; e < NEXP; e++) {
            if (e == i0) continue;
            if (i1 < 0 || v[e] > v[i1]) i1 = e;
        }
        float e1 = expf(v[i1] - v[i0]);
        float inv = 1.0f / (1.0f + e1);
        int s0 = atomicAdd(&g_cnt[i0], 1);
        int s1 = atomicAdd(&g_cnt[i1], 1);
        g_topi[t * 2] = i0;  g_topi[t * 2 + 1] = i1;
        g_topw[t * 2] = inv; g_topw[t * 2 + 1] = e1 * inv;
        g_slot[t * 2] = s0;  g_slot[t * 2 + 1] = s1;
    }
}

__global__ void gather_kernel(const float* __restrict__ h)
{
    int a = blockIdx.x;
    int t = a >> 1;
    int e = g_topi[a], s = g_slot[a];
    float* dst = g_xe + ((size_t)e * TT + s) * CC;
    const float* src = h + (size_t)t * CC;
    for (int i = threadIdx.x; i < CC; i += 256) dst[i] = src[i];
}

__global__ void scatter_kernel(float* __restrict__ x)
{
    int t = blockIdx.x;
    int e0 = g_topi[t * 2], e1 = g_topi[t * 2 + 1];
    int s0 = g_slot[t * 2], s1 = g_slot[t * 2 + 1];
    float w0 = g_topw[t * 2], w1 = g_topw[t * 2 + 1];
    const float* y0 = g_ey + ((size_t)e0 * TT + s0) * CC;
    const float* y1 = g_ey + ((size_t)e1 * TT + s1) * CC;
    for (int i = threadIdx.x; i < CC; i += 256)
        x[(size_t)t * CC + i] += w0 * y0[i] + w1 * y1[i];
}

// ---------------- host ----------------
static float *px, *ph, *pqkv, *pwqkv, *po, *pt, *pm1, *pm2, *pxe, *peg, *peu, *pey;
static int   *pcnt;
static bool  g_init = false;

static void init_ptrs()
{
    cudaGetSymbolAddress((void**)&px,    g_x);
    cudaGetSymbolAddress((void**)&ph,    g_h);
    cudaGetSymbolAddress((void**)&pqkv,  g_qkv);
    cudaGetSymbolAddress((void**)&pwqkv, g_wqkv);
    cudaGetSymbolAddress((void**)&po,    g_o);
    cudaGetSymbolAddress((void**)&pt,    g_t);
    cudaGetSymbolAddress((void**)&pm1,   g_m1);
    cudaGetSymbolAddress((void**)&pm2,   g_m2);
    cudaGetSymbolAddress((void**)&pxe,   g_xe);
    cudaGetSymbolAddress((void**)&peg,   g_eg);
    cudaGetSymbolAddress((void**)&peu,   g_eu);
    cudaGetSymbolAddress((void**)&pey,   g_ey);
    cudaGetSymbolAddress((void**)&pcnt,  g_cnt);
    cudaFuncSetAttribute(wgemm_kernel<64>,  cudaFuncAttributeMaxDynamicSharedMemorySize, SMEM_G64);
    cudaFuncSetAttribute(wgemm_kernel<128>, cudaFuncAttributeMaxDynamicSharedMemorySize, SMEM_G128);
    cudaFuncSetAttribute(attn_scores_w,     cudaFuncAttributeMaxDynamicSharedMemorySize, SMEM_ATT);
    cudaFuncSetAttribute(attn_pv_w,         cudaFuncAttributeMaxDynamicSharedMemorySize, SMEM_ATT);
    g_init = true;
}

// bm128=false -> BM=64
static inline void wg(const float* A, const float* A2, const float* B, float* C,
                      int M, int N, int K, int lda, int ldc,
                      size_t sA = 0, size_t sB = 0, size_t sC = 0,
                      const int* cnt = nullptr, int batch = 1, bool bm128 = false)
{
    if (bm128) {
        dim3 grid((N + 127) / 128, M / 128, batch);
        wgemm_kernel<128><<<grid, 256, SMEM_G128>>>(A, A2, B, C, N, K, lda, ldc, sA, sB, sC, cnt);
    } else {
        dim3 grid((N + 127) / 128, M / 64, batch);
        wgemm_kernel<64><<<grid, 256, SMEM_G64>>>(A, A2, B, C, N, K, lda, ldc, sA, sB, sC, cnt);
    }
}

extern "C" void kernel_launch(void* const* d_in, const int* in_sizes, int n_in,
                              void* d_out, int out_size)
{
    if (!g_init) init_ptrs();

    const int*   idx      = (const int*)  d_in[0];
    const float* wte      = (const float*)d_in[1];
    const float* Wq       = (const float*)d_in[2];
    const float* Wk       = (const float*)d_in[3];
    const float* Wv       = (const float*)d_in[4];
    const float* Wo       = (const float*)d_in[5];
    const float* ln1      = (const float*)d_in[6];
    const float* ln2      = (const float*)d_in[7];
    const float* dense_wg = (const float*)d_in[8];
    const float* dense_wu = (const float*)d_in[9];
    const float* dense_wd = (const float*)d_in[10];
    const float* gate_w   = (const float*)d_in[11];
    const float* exp_wg   = (const float*)d_in[12];
    const float* exp_wu   = (const float*)d_in[13];
    const float* exp_wd   = (const float*)d_in[14];
    const float* sh_wg    = (const float*)d_in[15];
    const float* sh_wu    = (const float*)d_in[16];
    const float* sh_wd    = (const float*)d_in[17];
    const float* lnf      = (const float*)d_in[18];
    const float* lm_head  = (const float*)d_in[19];
    float*       out      = (float*)d_out;

    embed_kernel<<<TT, 256>>>(idx, wte);

    for (int l = 0; l < NLAYER; l++) {
        // ---- attention ----
        rmsnorm_kernel<<<TT, 256>>>(px, ln1 + (size_t)l * CC, ph);
        pack_qkv_kernel<<<CC, 256>>>(Wq + (size_t)l * CC * CC,
                                     Wk + (size_t)l * CC * 256,
                                     Wv + (size_t)l * CC * 256);
        wg(ph, nullptr, pwqkv, pqkv, TT, QKVN, CC, CC, QKVN);
        rope_kernel<<<dim3(TT, NHEAD), 32>>>(pqkv, QKVN);
        rope_kernel<<<dim3(TT, NKVH),  32>>>(pqkv + 1024, QKVN);
        attn_scores_w<<<dim3(TT / 64, TT / 64, NHEAD), 256, SMEM_ATT>>>();
        softmax_kernel<<<dim3(TT, NHEAD), 256>>>();
        attn_pv_w<<<dim3(TT / 64, NHEAD), 256, SMEM_ATT>>>();
        wg(po, nullptr, Wo + (size_t)l * CC * CC, pt, TT, CC, CC, CC, CC);
        add_kernel<<<(TT * CC) / 256, 256>>>(px, pt, TT * CC);

        // ---- MLP / MoE ----
        rmsnorm_kernel<<<TT, 256>>>(px, ln2 + (size_t)l * CC, ph);
        if (l == 0) {
            wg(ph, nullptr, dense_wg, pm1, TT, HIDN, CC, CC, HP);
            wg(ph, nullptr, dense_wu, pm2, TT, HIDN, CC, CC, HP);
            wg(pm1, pm2, dense_wd, pt, TT, CC, HIDN, HP, CC);
            add_kernel<<<(TT * CC) / 256, 256>>>(px, pt, TT * CC);
        } else {
            int j = l - 1;
            // shared expert
            wg(ph, nullptr, sh_wg + (size_t)j * CC * HIDN, pm1, TT, HIDN, CC, CC, HP);
            wg(ph, nullptr, sh_wu + (size_t)j * CC * HIDN, pm2, TT, HIDN, CC, CC, HP);
            wg(pm1, pm2, sh_wd + (size_t)j * HIDN * CC, pt, TT, CC, HIDN, HP, CC);
            add_kernel<<<(TT * CC) / 256, 256>>>(px, pt, TT * CC);
            // routed experts (top-2)
            reset_cnt_kernel<<<1, 32>>>();
            gate_kernel<<<TT, 128>>>(ph, gate_w + (size_t)j * CC * NEXP);
            gather_kernel<<<TT * TOPK, 256>>>(ph);
            wg(pxe, nullptr, exp_wg + (size_t)j * NEXP * CC * HIDN, peg,
               TT, HIDN, CC, CC, HP,
               (size_t)TT * CC, (size_t)CC * HIDN, (size_t)TT * HP, pcnt, NEXP, true);
            wg(pxe, nullptr, exp_wu + (size_t)j * NEXP * CC * HIDN, peu,
               TT, HIDN, CC, CC, HP,
               (size_t)TT * CC, (size_t)CC * HIDN, (size_t)TT * HP, pcnt, NEXP, true);
            wg(peg, peu, exp_wd + (size_t)j * NEXP * HIDN * CC, pey,
               TT, CC, HIDN, HP, CC,
               (size_t)TT * HP, (size_t)HIDN * CC, (size_t)TT * CC, pcnt, NEXP);
            scatter_kernel<<<TT, 256>>>(px);
        }
    }

    // ---- final norm + lm_head ----
    rmsnorm_kernel<<<TT, 256>>>(px, lnf, ph);
    wg(ph, nullptr, lm_head, out, TT, VOCAB, CC, CC, VOCAB, 0, 0, 0, nullptr, 1, true);
}

// round 12
// speedup vs baseline: 1.1832x; 1.1832x over previous
#include <cuda_runtime.h>
#include <cuda_bf16.h>
#include <mma.h>
#include <math.h>

using namespace nvcuda;

#define TT     1024
#define CC     1024
#define NHEAD  16
#define NKVH   4
#define HDIM   64
#define QKVN   1536   // 1024 + 256 + 256
#define HIDN   2736
#define HP     2816   // padded hidden (22*128)
#define NLAYER 4
#define NEXP   8
#define TOPK   2
#define VOCAB  32000

#define SMEM_ATT   (4 * 64 * 68 * 4)             // 69632 bytes

// ---------------- scratch ----------------
__device__ float g_x   [TT*CC];
__device__ float g_h   [TT*CC];
__device__ float g_qkv [TT*QKVN];
__device__ float g_wqkv[CC*QKVN];
__device__ float g_s   [(size_t)NHEAD*TT*TT];
__device__ float g_o   [TT*CC];
__device__ float g_t   [TT*CC];
__device__ float g_m1  [TT*HP];
__device__ float g_m2  [TT*HP];
__device__ float g_xe  [(size_t)NEXP*TT*CC];
__device__ float g_eg  [(size_t)NEXP*TT*HP];
__device__ float g_eu  [(size_t)NEXP*TT*HP];
__device__ float g_ey  [(size_t)NEXP*TT*CC];
__device__ int   g_cnt [NEXP];
__device__ int   g_topi[TT*TOPK];
__device__ float g_topw[TT*TOPK];
__device__ int   g_slot[TT*TOPK];

// ---------------- 3xTF32 wmma GEMM (register split, 2-block residency) ----------------
// C(MxN) = A(MxK) @ B(KxN). Split in registers after smem load:
//   hi = tf32(x), lo = tf32(x - hi); a*b ~= alo*bhi + ahi*blo + ahi*bhi
// Optional A2: A_eff = silu(A)*A2. Batched via blockIdx.z; cnt[] early-exit.
// BM=64, BN=128, BK=16, 256 threads (warps 2x4), forced 2 blocks/SM.
__global__ void __launch_bounds__(256, 2) wgemm_kernel(
    const float* __restrict__ A, const float* __restrict__ A2,
    const float* __restrict__ B, float* __restrict__ C,
    int N, int K, int lda, int ldc,
    size_t sA, size_t sB, size_t sC, const int* __restrict__ cnt)
{
    constexpr int BM = 64, BN = 128, BK = 16;

    const int bz = blockIdx.z;
    if (cnt && (int)(blockIdx.y * BM) >= cnt[bz]) return;

    const float* Ab  = A + (size_t)bz * sA + (size_t)blockIdx.y * BM * lda;
    const float* A2b = A2 ? (A2 + (size_t)bz * sA + (size_t)blockIdx.y * BM * lda) : nullptr;
    const float* Bb  = B + (size_t)bz * sB;
    float*       Cb  = C + (size_t)bz * sC + (size_t)blockIdx.y * BM * ldc + (size_t)blockIdx.x * BN;
    const int n0 = blockIdx.x * BN;

    __shared__ float As[2][BM][20];
    __shared__ float Bs[2][BK][BN + 4];

    const int tid = threadIdx.x;
    const int wid = tid >> 5;
    const int wm  = wid >> 2;            // 0..1
    const int wn  = wid & 3;             // 0..3

    wmma::fragment<wmma::accumulator, 16, 16, 8, float> acc[2][2];
    #pragma unroll
    for (int i = 0; i < 2; i++)
        #pragma unroll
        for (int j = 0; j < 2; j++)
            wmma::fill_fragment(acc[i][j], 0.0f);

    const int KT = K / BK;
    float4 ra, rb[2];

    auto loadA = [&](int kt) {
        int row = tid >> 2, c4 = tid & 3;
        float4 v = *(const float4*)(Ab + (size_t)row * lda + kt * BK + c4 * 4);
        if (A2b) {
            float4 v2 = *(const float4*)(A2b + (size_t)row * lda + kt * BK + c4 * 4);
            v.x = (v.x / (1.0f + expf(-v.x))) * v2.x;
            v.y = (v.y / (1.0f + expf(-v.y))) * v2.y;
            v.z = (v.z / (1.0f + expf(-v.z))) * v2.z;
            v.w = (v.w / (1.0f + expf(-v.w))) * v2.w;
        }
        ra = v;
    };
    auto loadB = [&](int kt) {
        #pragma unroll
        for (int u = 0; u < 2; u++) {
            int f = tid + u * 256;
            int row = f >> 5, c4 = f & 31;
            int col = n0 + c4 * 4;
            rb[u] = (col < N) ? *(const float4*)(Bb + (size_t)(kt * BK + row) * N + col)
                              : make_float4(0.f, 0.f, 0.f, 0.f);
        }
    };
    auto stA = [&](int buf) {
        int row = tid >> 2, c4 = tid & 3;
        *(float4*)&As[buf][row][c4 * 4] = ra;
    };
    auto stB = [&](int buf) {
        #pragma unroll
        for (int u = 0; u < 2; u++) {
            int f = tid + u * 256;
            int row = f >> 5, c4 = f & 31;
            *(float4*)&Bs[buf][row][c4 * 4] = rb[u];
        }
    };

    loadA(0); loadB(0); stA(0); stB(0);
    __syncthreads();

    for (int kt = 0; kt < KT; kt++) {
        const int cur = kt & 1;
        if (kt + 1 < KT) { loadA(kt + 1); loadB(kt + 1); }

        #pragma unroll
        for (int ks = 0; ks < 2; ks++) {
            wmma::fragment<wmma::matrix_a, 16, 16, 8, wmma::precision::tf32, wmma::row_major> ahi[2], alo[2];
            wmma::fragment<wmma::matrix_b, 16, 16, 8, wmma::precision::tf32, wmma::row_major> bhi[2], blo[2];
            #pragma unroll
            for (int i = 0; i < 2; i++) {
                wmma::load_matrix_sync(ahi[i], &As[cur][wm * 32 + i * 16][ks * 8], 20);
                #pragma unroll
                for (int t = 0; t < ahi[i].num_elements; t++) {
                    float x = ahi[i].x[t];
                    float h = wmma::__float_to_tf32(x);
                    ahi[i].x[t] = h;
                    alo[i].x[t] = wmma::__float_to_tf32(x - h);
                }
            }
            #pragma unroll
            for (int j = 0; j < 2; j++) {
                wmma::load_matrix_sync(bhi[j], &Bs[cur][ks * 8][wn * 32 + j * 16], BN + 4);
                #pragma unroll
                for (int t = 0; t < bhi[j].num_elements; t++) {
                    float x = bhi[j].x[t];
                    float h = wmma::__float_to_tf32(x);
                    bhi[j].x[t] = h;
                    blo[j].x[t] = wmma::__float_to_tf32(x - h);
                }
            }
            #pragma unroll
            for (int i = 0; i < 2; i++)
                #pragma unroll
                for (int j = 0; j < 2; j++) {
                    wmma::mma_sync(acc[i][j], alo[i], bhi[j], acc[i][j]);
                    wmma::mma_sync(acc[i][j], ahi[i], blo[j], acc[i][j]);
                    wmma::mma_sync(acc[i][j], ahi[i], bhi[j], acc[i][j]);
                }
        }

        if (kt + 1 < KT) { stA(1 - cur); stB(1 - cur); }
        __syncthreads();
    }

    #pragma unroll
    for (int i = 0; i < 2; i++)
        #pragma unroll
        for (int j = 0; j < 2; j++)
            wmma::store_matrix_sync(Cb + (size_t)(wm * 32 + i * 16) * ldc + wn * 32 + j * 16,
                                    acc[i][j], ldc, wmma::mem_row_major);
}

// ---------------- small ops ----------------
__global__ void pack_qkv_kernel(const float* __restrict__ Wq, const float* __restrict__ Wk,
                                const float* __restrict__ Wv)
{
    int r = blockIdx.x;
    for (int c = threadIdx.x; c < QKVN; c += 256) {
        float v;
        if (c < 1024)      v = Wq[(size_t)r * CC + c];
        else if (c < 1280) v = Wk[(size_t)r * 256 + (c - 1024)];
        else               v = Wv[(size_t)r * 256 + (c - 1280)];
        g_wqkv[(size_t)r * QKVN + c] = v;
    }
}

__global__ void embed_kernel(const int* __restrict__ idx, const float* __restrict__ wte)
{
    int t = blockIdx.x;
    int r = idx[t];
    for (int i = threadIdx.x; i < CC; i += 256)
        g_x[(size_t)t * CC + i] = wte[(size_t)r * CC + i];
}

__global__ void rmsnorm_kernel(const float* __restrict__ x, const float* __restrict__ w,
                               float* __restrict__ o)
{
    int t = blockIdx.x, tid = threadIdx.x;
    const float* xr = x + (size_t)t * CC;
    __shared__ float red[256];
    float s = 0.0f;
    for (int i = tid; i < CC; i += 256) { float v = xr[i]; s += v * v; }
    red[tid] = s; __syncthreads();
    for (int st = 128; st; st >>= 1) { if (tid < st) red[tid] += red[tid + st]; __syncthreads(); }
    float scale = rsqrtf(red[0] / CC + 1e-6f);
    for (int i = tid; i < CC; i += 256)
        o[(size_t)t * CC + i] = xr[i] * scale * w[i];
}

__global__ void add_kernel(float* __restrict__ y, const float* __restrict__ a, int n)
{
    int i = blockIdx.x * 256 + threadIdx.x;
    if (i < n) y[i] += a[i];
}

__global__ void rope_kernel(float* __restrict__ buf, int ld)   // grid (T, nheads), 32 thr
{
    int t = blockIdx.x, h = blockIdx.y, j = threadIdx.x;
    float inv = powf(10000.0f, -(float)j / 32.0f);
    float ang = (float)t * inv;
    float c = cosf(ang), sn = sinf(ang);
    float* p = buf + (size_t)t * ld + h * HDIM;
    float a = p[j], b = p[j + 32];
    p[j]      = a * c - b * sn;
    p[j + 32] = a * sn + b * c;
}

// ---------------- attention: split-tf32 wmma scores / PV ----------------
__global__ void __launch_bounds__(256) attn_scores_w()   // grid (kt, qt, NHEAD)
{
    int kt = blockIdx.x, qt = blockIdx.y, h = blockIdx.z;
    if (kt > qt) return;
    extern __shared__ float sm[];
    float* Qh = sm;
    float* Ql = sm + 64 * 68;
    float* Kh = sm + 2 * 64 * 68;
    float* Kl = sm + 3 * 64 * 68;
    int tid = threadIdx.x;
    const float* qb = g_qkv + (size_t)qt * 64 * QKVN + h * HDIM;
    const float* kb = g_qkv + 1024 + (size_t)kt * 64 * QKVN + (h >> 2) * HDIM;

    for (int i = tid; i < 4096; i += 256) {
        int m = i >> 6, d = i & 63;
        float q  = qb[(size_t)m * QKVN + d];
        float qh = wmma::__float_to_tf32(q);
        Qh[m * 68 + d] = qh;
        Ql[m * 68 + d] = wmma::__float_to_tf32(q - qh);
        float k  = kb[(size_t)m * QKVN + d];
        float kh = wmma::__float_to_tf32(k);
        Kh[m * 68 + d] = kh;
        Kl[m * 68 + d] = wmma::__float_to_tf32(k - kh);
    }
    __syncthreads();

    int wid = tid >> 5, wm = wid >> 2, wn = wid & 3;
    wmma::fragment<wmma::accumulator, 16, 16, 8, float> acc[2];
    wmma::fill_fragment(acc[0], 0.0f);
    wmma::fill_fragment(acc[1], 0.0f);

    #pragma unroll
    for (int kk = 0; kk < 8; kk++) {
        wmma::fragment<wmma::matrix_a, 16, 16, 8, wmma::precision::tf32, wmma::row_major> ahi[2], alo[2];
        wmma::fragment<wmma::matrix_b, 16, 16, 8, wmma::precision::tf32, wmma::col_major> bhi, blo;
        #pragma unroll
        for (int i = 0; i < 2; i++) {
            wmma::load_matrix_sync(ahi[i], Qh + (wm * 32 + i * 16) * 68 + kk * 8, 68);
            wmma::load_matrix_sync(alo[i], Ql + (wm * 32 + i * 16) * 68 + kk * 8, 68);
        }
        wmma::load_matrix_sync(bhi, Kh + (wn * 16) * 68 + kk * 8, 68);
        wmma::load_matrix_sync(blo, Kl + (wn * 16) * 68 + kk * 8, 68);
        #pragma unroll
        for (int i = 0; i < 2; i++) {
            wmma::mma_sync(acc[i], alo[i], bhi, acc[i]);
            wmma::mma_sync(acc[i], ahi[i], blo, acc[i]);
            wmma::mma_sync(acc[i], ahi[i], bhi, acc[i]);
        }
    }
    __syncthreads();
    float* S = sm;
    #pragma unroll
    for (int i = 0; i < 2; i++)
        wmma::store_matrix_sync(S + (wm * 32 + i * 16) * 68 + wn * 16, acc[i], 68, wmma::mem_row_major);
    __syncthreads();
    for (int i = tid; i < 4096; i += 256) {
        int m = i >> 6, d = i & 63;
        int qi = qt * 64 + m, ki = kt * 64 + d;
        g_s[((size_t)h * TT + qi) * TT + ki] = (ki <= qi) ? S[m * 68 + d] * 0.125f : -1e9f;
    }
}

__global__ void __launch_bounds__(256) attn_pv_w()       // grid (qt, NHEAD)
{
    int qt = blockIdx.x, h = blockIdx.y;
    extern __shared__ float sm[];
    float* Ph = sm;
    float* Pl = sm + 64 * 68;
    float* Vh = sm + 2 * 64 * 68;
    float* Vl = sm + 3 * 64 * 68;
    int tid = threadIdx.x;
    int wid = tid >> 5, wm = wid >> 2, wn = wid & 3;
    const float* pb = g_s + ((size_t)h * TT + (size_t)qt * 64) * TT;
    const float* vb = g_qkv + 1280 + (h >> 2) * HDIM;

    wmma::fragment<wmma::accumulator, 16, 16, 8, float> acc[2];
    wmma::fill_fragment(acc[0], 0.0f);
    wmma::fill_fragment(acc[1], 0.0f);

    for (int kt = 0; kt <= qt; kt++) {
        __syncthreads();
        for (int i = tid; i < 4096; i += 256) {
            int m = i >> 6, n = i & 63;
            float p  = pb[(size_t)m * TT + kt * 64 + n];
            float ph = wmma::__float_to_tf32(p);
            Ph[m * 68 + n] = ph;
            Pl[m * 68 + n] = wmma::__float_to_tf32(p - ph);
            float v  = vb[(size_t)(kt * 64 + m) * QKVN + n];
            float vh = wmma::__float_to_tf32(v);
            Vh[m * 68 + n] = vh;
            Vl[m * 68 + n] = wmma::__float_to_tf32(v - vh);
        }
        __syncthreads();
        #pragma unroll
        for (int kk = 0; kk < 8; kk++) {
            wmma::fragment<wmma::matrix_a, 16, 16, 8, wmma::precision::tf32, wmma::row_major> ahi[2], alo[2];
            wmma::fragment<wmma::matrix_b, 16, 16, 8, wmma::precision::tf32, wmma::row_major> bhi, blo;
            #pragma unroll
            for (int i = 0; i < 2; i++) {
                wmma::load_matrix_sync(ahi[i], Ph + (wm * 32 + i * 16) * 68 + kk * 8, 68);
                wmma::load_matrix_sync(alo[i], Pl + (wm * 32 + i * 16) * 68 + kk * 8, 68);
            }
            wmma::load_matrix_sync(bhi, Vh + (kk * 8) * 68 + wn * 16, 68);
            wmma::load_matrix_sync(blo, Vl + (kk * 8) * 68 + wn * 16, 68);
            #pragma unroll
            for (int i = 0; i < 2; i++) {
                wmma::mma_sync(acc[i], alo[i], bhi, acc[i]);
                wmma::mma_sync(acc[i], ahi[i], blo, acc[i]);
                wmma::mma_sync(acc[i], ahi[i], bhi, acc[i]);
            }
        }
    }
    #pragma unroll
    for (int i = 0; i < 2; i++)
        wmma::store_matrix_sync(g_o + (size_t)(qt * 64 + wm * 32 + i * 16) * CC + h * HDIM + wn * 16,
                                acc[i], CC, wmma::mem_row_major);
}

__global__ void softmax_kernel()         // grid (T, NHEAD), 256 thr
{
    int qi = blockIdx.x, h = blockIdx.y, tid = threadIdx.x;
    float* row = g_s + ((size_t)h * TT + qi) * TT;
    int len = ((qi >> 6) + 1) << 6;
    __shared__ float red[256];
    float m = -1e30f;
    for (int i = tid; i < len; i += 256) m = fmaxf(m, row[i]);
    red[tid] = m; __syncthreads();
    for (int st = 128; st; st >>= 1) { if (tid < st) red[tid] = fmaxf(red[tid], red[tid + st]); __syncthreads(); }
    m = red[0]; __syncthreads();
    float sum = 0.0f;
    for (int i = tid; i < len; i += 256) { float e = expf(row[i] - m); row[i] = e; sum += e; }
    red[tid] = sum; __syncthreads();
    for (int st = 128; st; st >>= 1) { if (tid < st) red[tid] += red[tid + st]; __syncthreads(); }
    float inv = 1.0f / red[0];
    for (int i = tid; i < len; i += 256) row[i] *= inv;
}

// ---------------- MoE routing ----------------
__global__ void reset_cnt_kernel()
{
    if (threadIdx.x < NEXP) g_cnt[threadIdx.x] = 0;
}

__global__ void gate_kernel(const float* __restrict__ h, const float* __restrict__ gw)
{
    int t = blockIdx.x, tid = threadIdx.x;
    __shared__ float red[128][NEXP];
    float acc[NEXP] = {};
    const float* hr = h + (size_t)t * CC;
    for (int c = tid; c < CC; c += 128) {
        float xv = hr[c];
        #pragma unroll
        for (int e = 0; e < NEXP; e++) acc[e] = fmaf(xv, gw[c * NEXP + e], acc[e]);
    }
    #pragma unroll
    for (int e = 0; e < NEXP; e++) red[tid][e] = acc[e];
    __syncthreads();
    for (int st = 64; st; st >>= 1) {
        if (tid < st)
            #pragma unroll
            for (int e = 0; e < NEXP; e++) red[tid][e] += red[tid + st][e];
        __syncthreads();
    }
    if (tid == 0) {
        float v[NEXP];
        #pragma unroll
        for (int e = 0; e < NEXP; e++) v[e] = red[0][e];
        int i0 = 0;
        for (int e = 1; e < NEXP; e++) if (v[e] > v[i0]) i0 = e;
        int i1 = -1;
        for (int e = 0; e < NEXP; e++) {
            if (e == i0) continue;
            if (i1 < 0 || v[e] > v[i1]) i1 = e;
        }
        float e1 = expf(v[i1] - v[i0]);
        float inv = 1.0f / (1.0f + e1);
        int s0 = atomicAdd(&g_cnt[i0], 1);
        int s1 = atomicAdd(&g_cnt[i1], 1);
        g_topi[t * 2] = i0;  g_topi[t * 2 + 1] = i1;
        g_topw[t * 2] = inv; g_topw[t * 2 + 1] = e1 * inv;
        g_slot[t * 2] = s0;  g_slot[t * 2 + 1] = s1;
    }
}

__global__ void gather_kernel(const float* __restrict__ h)
{
    int a = blockIdx.x;
    int t = a >> 1;
    int e = g_topi[a], s = g_slot[a];
    float* dst = g_xe + ((size_t)e * TT + s) * CC;
    const float* src = h + (size_t)t * CC;
    for (int i = threadIdx.x; i < CC; i += 256) dst[i] = src[i];
}

__global__ void scatter_kernel(float* __restrict__ x)
{
    int t = blockIdx.x;
    int e0 = g_topi[t * 2], e1 = g_topi[t * 2 + 1];
    int s0 = g_slot[t * 2], s1 = g_slot[t * 2 + 1];
    float w0 = g_topw[t * 2], w1 = g_topw[t * 2 + 1];
    const float* y0 = g_ey + ((size_t)e0 * TT + s0) * CC;
    const float* y1 = g_ey + ((size_t)e1 * TT + s1) * CC;
    for (int i = threadIdx.x; i < CC; i += 256)
        x[(size_t)t * CC + i] += w0 * y0[i] + w1 * y1[i];
}

// ---------------- host ----------------
static float *px, *ph, *pqkv, *pwqkv, *po, *pt, *pm1, *pm2, *pxe, *peg, *peu, *pey;
static int   *pcnt;
static bool  g_init = false;

static void init_ptrs()
{
    cudaGetSymbolAddress((void**)&px,    g_x);
    cudaGetSymbolAddress((void**)&ph,    g_h);
    cudaGetSymbolAddress((void**)&pqkv,  g_qkv);
    cudaGetSymbolAddress((void**)&pwqkv, g_wqkv);
    cudaGetSymbolAddress((void**)&po,    g_o);
    cudaGetSymbolAddress((void**)&pt,    g_t);
    cudaGetSymbolAddress((void**)&pm1,   g_m1);
    cudaGetSymbolAddress((void**)&pm2,   g_m2);
    cudaGetSymbolAddress((void**)&pxe,   g_xe);
    cudaGetSymbolAddress((void**)&peg,   g_eg);
    cudaGetSymbolAddress((void**)&peu,   g_eu);
    cudaGetSymbolAddress((void**)&pey,   g_ey);
    cudaGetSymbolAddress((void**)&pcnt,  g_cnt);
    cudaFuncSetAttribute(attn_scores_w, cudaFuncAttributeMaxDynamicSharedMemorySize, SMEM_ATT);
    cudaFuncSetAttribute(attn_pv_w,     cudaFuncAttributeMaxDynamicSharedMemorySize, SMEM_ATT);
    g_init = true;
}

static inline void wg(const float* A, const float* A2, const float* B, float* C,
                      int M, int N, int K, int lda, int ldc,
                      size_t sA = 0, size_t sB = 0, size_t sC = 0,
                      const int* cnt = nullptr, int batch = 1)
{
    dim3 grid((N + 127) / 128, M / 64, batch);
    wgemm_kernel<<<grid, 256>>>(A, A2, B, C, N, K, lda, ldc, sA, sB, sC, cnt);
}

extern "C" void kernel_launch(void* const* d_in, const int* in_sizes, int n_in,
                              void* d_out, int out_size)
{
    if (!g_init) init_ptrs();

    const int*   idx      = (const int*)  d_in[0];
    const float* wte      = (const float*)d_in[1];
    const float* Wq       = (const float*)d_in[2];
    const float* Wk       = (const float*)d_in[3];
    const float* Wv       = (const float*)d_in[4];
    const float* Wo       = (const float*)d_in[5];
    const float* ln1      = (const float*)d_in[6];
    const float* ln2      = (const float*)d_in[7];
    const float* dense_wg = (const float*)d_in[8];
    const float* dense_wu = (const float*)d_in[9];
    const float* dense_wd = (const float*)d_in[10];
    const float* gate_w   = (const float*)d_in[11];
    const float* exp_wg   = (const float*)d_in[12];
    const float* exp_wu   = (const float*)d_in[13];
    const float* exp_wd   = (const float*)d_in[14];
    const float* sh_wg    = (const float*)d_in[15];
    const float* sh_wu    = (const float*)d_in[16];
    const float* sh_wd    = (const float*)d_in[17];
    const float* lnf      = (const float*)d_in[18];
    const float* lm_head  = (const float*)d_in[19];
    float*       out      = (float*)d_out;

    embed_kernel<<<TT, 256>>>(idx, wte);

    for (int l = 0; l < NLAYER; l++) {
        // ---- attention ----
        rmsnorm_kernel<<<TT, 256>>>(px, ln1 + (size_t)l * CC, ph);
        pack_qkv_kernel<<<CC, 256>>>(Wq + (size_t)l * CC * CC,
                                     Wk + (size_t)l * CC * 256,
                                     Wv + (size_t)l * CC * 256);
        wg(ph, nullptr, pwqkv, pqkv, TT, QKVN, CC, CC, QKVN);
        rope_kernel<<<dim3(TT, NHEAD), 32>>>(pqkv, QKVN);
        rope_kernel<<<dim3(TT, NKVH),  32>>>(pqkv + 1024, QKVN);
        attn_scores_w<<<dim3(TT / 64, TT / 64, NHEAD), 256, SMEM_ATT>>>();
        softmax_kernel<<<dim3(TT, NHEAD), 256>>>();
        attn_pv_w<<<dim3(TT / 64, NHEAD), 256, SMEM_ATT>>>();
        wg(po, nullptr, Wo + (size_t)l * CC * CC, pt, TT, CC, CC, CC, CC);
        add_kernel<<<(TT * CC) / 256, 256>>>(px, pt, TT * CC);

        // ---- MLP / MoE ----
        rmsnorm_kernel<<<TT, 256>>>(px, ln2 + (size_t)l * CC, ph);
        if (l == 0) {
            wg(ph, nullptr, dense_wg, pm1, TT, HIDN, CC, CC, HP);
            wg(ph, nullptr, dense_wu, pm2, TT, HIDN, CC, CC, HP);
            wg(pm1, pm2, dense_wd, pt, TT, CC, HIDN, HP, CC);
            add_kernel<<<(TT * CC) / 256, 256>>>(px, pt, TT * CC);
        } else {
            int j = l - 1;
            // shared expert
            wg(ph, nullptr, sh_wg + (size_t)j * CC * HIDN, pm1, TT, HIDN, CC, CC, HP);
            wg(ph, nullptr, sh_wu + (size_t)j * CC * HIDN, pm2, TT, HIDN, CC, CC, HP);
            wg(pm1, pm2, sh_wd + (size_t)j * HIDN * CC, pt, TT, CC, HIDN, HP, CC);
            add_kernel<<<(TT * CC) / 256, 256>>>(px, pt, TT * CC);
            // routed experts (top-2)
            reset_cnt_kernel<<<1, 32>>>();
            gate_kernel<<<TT, 128>>>(ph, gate_w + (size_t)j * CC * NEXP);
            gather_kernel<<<TT * TOPK, 256>>>(ph);
            wg(pxe, nullptr, exp_wg + (size_t)j * NEXP * CC * HIDN, peg,
               TT, HIDN, CC, CC, HP,
               (size_t)TT * CC, (size_t)CC * HIDN, (size_t)TT * HP, pcnt, NEXP);
            wg(pxe, nullptr, exp_wu + (size_t)j * NEXP * CC * HIDN, peu,
               TT, HIDN, CC, CC, HP,
               (size_t)TT * CC, (size_t)CC * HIDN, (size_t)TT * HP, pcnt, NEXP);
            wg(peg, peu, exp_wd + (size_t)j * NEXP * HIDN * CC, pey,
               TT, CC, HIDN, HP, CC,
               (size_t)TT * HP, (size_t)HIDN * CC, (size_t)TT * CC, pcnt, NEXP);
            scatter_kernel<<<TT, 256>>>(px);
        }
    }

    // ---- final norm + lm_head ----
    rmsnorm_kernel<<<TT, 256>>>(px, lnf, ph);
    wg(ph, nullptr, lm_head, out, TT, VOCAB, CC, CC, VOCAB);
}